// round 11
// baseline (speedup 1.0000x reference)
#include <cuda_runtime.h>
#include <cuda_bf16.h>
#include <cooperative_groups.h>

namespace cg = cooperative_groups;

#define RB      4
#define BINS    64      // RB^3
#define BATCH   64
#define CLS     40
#define THREADS 1024
#define NWARP   (THREADS / 32)

#define CH_PTS  4096                // points per chunk
#define CH_F    (CH_PTS * 3)        // 12288 floats
#define CH_F4   (CH_F / 4)          // 3072 float4s (= 3 per thread)
#define DYN_BYTES (2 * CH_F * 4)    // 98304 B double buffer

__device__ __forceinline__ void cpa16(void* dst, const void* src) {
    unsigned d = (unsigned)__cvta_generic_to_shared(dst);
    asm volatile("cp.async.cg.shared.global [%0], [%1], 16;" :: "r"(d), "l"(src));
}
#define CPA_COMMIT() asm volatile("cp.async.commit_group;" ::: "memory")
#define CPA_WAIT1()  asm volatile("cp.async.wait_group 1;" ::: "memory")
#define CPA_WAIT0()  asm volatile("cp.async.wait_group 0;" ::: "memory")

// Stage chunk cIdx of this CTA's region into dstPtr (3 predicated copies/thread)
#define STAGE(cIdx, dstPtr)                                                  \
    do {                                                                     \
        int    base_ = (cIdx) * CH_F4;                                       \
        float4* d4_  = (float4*)(dstPtr);                                    \
        int    i0_   = base_ + tid;                                          \
        if (i0_ < totF4)        cpa16(&d4_[tid],        &src4[i0_]);         \
        if (i0_ + 1024 < totF4) cpa16(&d4_[tid + 1024], &src4[i0_ + 1024]);  \
        if (i0_ + 2048 < totF4) cpa16(&d4_[tid + 2048], &src4[i0_ + 2048]);  \
        CPA_COMMIT();                                                        \
    } while (0)

__global__ void __cluster_dims__(2, 1, 1) __launch_bounds__(THREADS, 1)
k_fused(const float* __restrict__ x, const float* __restrict__ W,
        const float* __restrict__ bias, float* __restrict__ out,
        int N, int S, float invN)
{
    extern __shared__ float dyn[];
    float* buf0 = dyn;
    float* buf1 = dyn + CH_F;

    __shared__ float sWt[BINS * CLS];   // W transposed: sWt[k*CLS + c]
    __shared__ int   sh[NWARP * BINS];  // per-warp sub-histograms
    __shared__ float sred[NWARP][6];
    __shared__ float sblk[6];           // this CTA's mn0..2, mx0..2
    __shared__ float sfin[6];           // cluster-combined
    __shared__ int   hfin[BINS];
    __shared__ float sc[BINS];

    cg::cluster_group cluster = cg::this_cluster();
    const int rank = cluster.block_rank();   // 0 or 1
    const int bat  = blockIdx.y;
    const int tid  = threadIdx.x;
    const int lane = tid & 31, warp = tid >> 5;

    // This CTA's region: rank0 -> points [0, S), rank1 -> [S, N). S % 4 == 0,
    // so both regions are float4-aligned (3*S % 4 == 0).
    const float* xb   = x + (size_t)bat * 3u * (size_t)N;
    const int    P    = rank ? (N - S) : S;
    const float4* src4 = (const float4*)(xb + (rank ? 3 * (size_t)S : 0));
    const int    totF4 = (3 * P) / 4;          // exact for bench shape
    const int    nCh   = (P + CH_PTS - 1) / CH_PTS;

    if (rank == 0) {
        for (int i = tid; i < CLS * BINS; i += THREADS) {
            int c = i >> 6, k = i & 63;
            sWt[k * CLS + c] = W[i];
        }
    }
    for (int i = tid; i < NWARP * BINS; i += THREADS) sh[i] = 0;

    // ============== Pass 1: min/max via cp.async pipeline =================
    const float FMAX = 3.402823466e38f;
    float mn0 = FMAX, mn1 = FMAX, mn2 = FMAX;
    float mx0 = -FMAX, mx1 = -FMAX, mx2 = -FMAX;

    STAGE(0, buf0);
    for (int c = 0; c < nCh; c++) {
        float* cur = (c & 1) ? buf1 : buf0;
        float* nxt = (c & 1) ? buf0 : buf1;
        if (c + 1 < nCh) { STAGE(c + 1, nxt); CPA_WAIT1(); }
        else             { CPA_WAIT0(); }
        __syncthreads();

        int pts  = min(CH_PTS, P - c * CH_PTS);
        int base = tid * 4;
        if (base < pts) {
            const float4* cp = (const float4*)(cur + tid * 12);
            float4 a = cp[0], b = cp[1], cc = cp[2];
            // points: (a.x,a.y,a.z) (a.w,b.x,b.y) (b.z,b.w,cc.x) (cc.y,cc.z,cc.w)
            if (base + 3 < pts) {
                mn0 = fminf(mn0, fminf(fminf(a.x, a.w), fminf(b.z, cc.y)));
                mx0 = fmaxf(mx0, fmaxf(fmaxf(a.x, a.w), fmaxf(b.z, cc.y)));
                mn1 = fminf(mn1, fminf(fminf(a.y, b.x), fminf(b.w, cc.z)));
                mx1 = fmaxf(mx1, fmaxf(fmaxf(a.y, b.x), fmaxf(b.w, cc.z)));
                mn2 = fminf(mn2, fminf(fminf(a.z, b.y), fminf(cc.x, cc.w)));
                mx2 = fmaxf(mx2, fmaxf(fmaxf(a.z, b.y), fmaxf(cc.x, cc.w)));
            } else {
                mn0 = fminf(mn0, a.x); mx0 = fmaxf(mx0, a.x);
                mn1 = fminf(mn1, a.y); mx1 = fmaxf(mx1, a.y);
                mn2 = fminf(mn2, a.z); mx2 = fmaxf(mx2, a.z);
                if (base + 1 < pts) {
                    mn0 = fminf(mn0, a.w); mx0 = fmaxf(mx0, a.w);
                    mn1 = fminf(mn1, b.x); mx1 = fmaxf(mx1, b.x);
                    mn2 = fminf(mn2, b.y); mx2 = fmaxf(mx2, b.y);
                }
                if (base + 2 < pts) {
                    mn0 = fminf(mn0, b.z); mx0 = fmaxf(mx0, b.z);
                    mn1 = fminf(mn1, b.w); mx1 = fmaxf(mx1, b.w);
                    mn2 = fminf(mn2, cc.x); mx2 = fmaxf(mx2, cc.x);
                }
            }
        }
        __syncthreads();
    }

    #pragma unroll
    for (int off = 16; off > 0; off >>= 1) {
        mn0 = fminf(mn0, __shfl_xor_sync(0xffffffffu, mn0, off));
        mn1 = fminf(mn1, __shfl_xor_sync(0xffffffffu, mn1, off));
        mn2 = fminf(mn2, __shfl_xor_sync(0xffffffffu, mn2, off));
        mx0 = fmaxf(mx0, __shfl_xor_sync(0xffffffffu, mx0, off));
        mx1 = fmaxf(mx1, __shfl_xor_sync(0xffffffffu, mx1, off));
        mx2 = fmaxf(mx2, __shfl_xor_sync(0xffffffffu, mx2, off));
    }
    if (lane == 0) {
        sred[warp][0] = mn0; sred[warp][1] = mn1; sred[warp][2] = mn2;
        sred[warp][3] = mx0; sred[warp][4] = mx1; sred[warp][5] = mx2;
    }
    __syncthreads();
    if (warp == 0) {   // NWARP == 32
        float v0 = sred[lane][0], v1 = sred[lane][1], v2 = sred[lane][2];
        float v3 = sred[lane][3], v4 = sred[lane][4], v5 = sred[lane][5];
        #pragma unroll
        for (int off = 16; off > 0; off >>= 1) {
            v0 = fminf(v0, __shfl_xor_sync(0xffffffffu, v0, off));
            v1 = fminf(v1, __shfl_xor_sync(0xffffffffu, v1, off));
            v2 = fminf(v2, __shfl_xor_sync(0xffffffffu, v2, off));
            v3 = fmaxf(v3, __shfl_xor_sync(0xffffffffu, v3, off));
            v4 = fmaxf(v4, __shfl_xor_sync(0xffffffffu, v4, off));
            v5 = fmaxf(v5, __shfl_xor_sync(0xffffffffu, v5, off));
        }
        if (lane == 0) {
            sblk[0] = v0; sblk[1] = v1; sblk[2] = v2;
            sblk[3] = v3; sblk[4] = v4; sblk[5] = v5;
        }
    }

    // ---- Cluster exchange of min/max ----
    cluster.sync();
    if (tid < 3) {
        const float* peer = cluster.map_shared_rank(sblk, rank ^ 1);
        sfin[tid]     = fminf(sblk[tid],     peer[tid]);
        sfin[tid + 3] = fmaxf(sblk[tid + 3], peer[tid + 3]);
    }
    __syncthreads();
    const float fm0 = sfin[0], fm1 = sfin[1], fm2 = sfin[2];
    // Shrunken scale + interior bias (no clamps) + magic-number floor
    // (FADD instead of F2I): z = fmaf(v,s,t) + 2^23, bin bits in mantissa.
    const float MAGIC = 8388608.0f;  // 2^23
    const float s0 = 3.99999f / (sfin[3] - fm0);
    const float s1 = 3.99999f / (sfin[4] - fm1);
    const float s2 = 3.99999f / (sfin[5] - fm2);
    const float t0 = (1e-6f - 0.5f) - fm0 * s0;
    const float t1 = (1e-6f - 0.5f) - fm1 * s1;
    const float t2 = (1e-6f - 0.5f) - fm2 * s2;

    // ============== Pass 2: histogram via cp.async pipeline ===============
    int* myh = &sh[warp << 6];

    #define BIN3(px, py, pz)                                                 \
        do {                                                                 \
            float z0_ = fmaf((px), s0, t0) + MAGIC;                          \
            float z1_ = fmaf((py), s1, t1) + MAGIC;                          \
            float z2_ = fmaf((pz), s2, t2) + MAGIC;                          \
            unsigned u0_ = __float_as_uint(z0_) & 3u;                        \
            unsigned u1_ = __float_as_uint(z1_) & 3u;                        \
            unsigned u2_ = __float_as_uint(z2_) & 3u;                        \
            atomicAdd(&myh[(u0_ << 4) | (u1_ << 2) | u2_], 1);               \
        } while (0)

    STAGE(0, buf0);
    for (int c = 0; c < nCh; c++) {
        float* cur = (c & 1) ? buf1 : buf0;
        float* nxt = (c & 1) ? buf0 : buf1;
        if (c + 1 < nCh) { STAGE(c + 1, nxt); CPA_WAIT1(); }
        else             { CPA_WAIT0(); }
        __syncthreads();

        int pts  = min(CH_PTS, P - c * CH_PTS);
        int base = tid * 4;
        if (base < pts) {
            const float4* cp = (const float4*)(cur + tid * 12);
            float4 a = cp[0], b = cp[1], cc = cp[2];
            if (base + 3 < pts) {
                BIN3(a.x, a.y, a.z);
                BIN3(a.w, b.x, b.y);
                BIN3(b.z, b.w, cc.x);
                BIN3(cc.y, cc.z, cc.w);
            } else {
                BIN3(a.x, a.y, a.z);
                if (base + 1 < pts) BIN3(a.w, b.x, b.y);
                if (base + 2 < pts) BIN3(b.z, b.w, cc.x);
            }
        }
        __syncthreads();
    }

    if (tid < BINS) {
        int s = 0;
        #pragma unroll
        for (int w = 0; w < NWARP; w++) s += sh[(w << 6) + tid];
        hfin[tid] = s;
    }

    // ---- Cluster hist merge + epilogue (rank 0) ----
    cluster.sync();
    if (rank == 0 && tid < BINS) {
        const int* peer = cluster.map_shared_rank(hfin, 1);
        sc[tid] = (float)(hfin[tid] + peer[tid]) * invN;
    }
    cluster.sync();   // rank 1 must not exit before rank 0 read its smem

    if (rank == 0) {
        __syncthreads();
        if (tid < CLS) {
            float acc = bias[tid];
            #pragma unroll
            for (int k = 0; k < BINS; k++)
                acc = fmaf(sc[k], sWt[k * CLS + tid], acc);
            out[bat * CLS + tid] = acc;
        }
    }
}

extern "C" void kernel_launch(void* const* d_in, const int* in_sizes, int n_in,
                              void* d_out, int out_size) {
    const float* x = (const float*)d_in[0];
    const float* W = (const float*)d_in[1];
    const float* b = (const float*)d_in[2];
    float* out = (float*)d_out;

    int N = in_sizes[0] / (BATCH * 3);   // 100000
    int S = (((N / 2) + 3) >> 2) << 2;   // rank split, multiple of 4 points

    cudaFuncSetAttribute(k_fused, cudaFuncAttributeMaxDynamicSharedMemorySize,
                         DYN_BYTES);

    dim3 grid(2, BATCH);
    k_fused<<<grid, THREADS, DYN_BYTES>>>(x, W, b, out, N, S, 1.0f / (float)N);
}

// round 12
// speedup vs baseline: 1.2786x; 1.2786x over previous
#include <cuda_runtime.h>
#include <cuda_bf16.h>
#include <cooperative_groups.h>

namespace cg = cooperative_groups;

#define RB      4
#define BINS    64      // RB^3
#define BATCH   64
#define CLS     40
#define THREADS 1024
#define NWARP   (THREADS / 32)
#define GSTRIDE (2 * NWARP)         // warp stride across the 2-CTA cluster

#define SLOT_F4 96                  // one tile = 96 float4 = 128 points
#define NSLOT   3                   // ring depth (2 tiles in flight)
#define DYN_BYTES (NWARP * NSLOT * SLOT_F4 * 16)   // 147456 B

__device__ __forceinline__ void cpa16(void* dst, const void* src) {
    unsigned d = (unsigned)__cvta_generic_to_shared(dst);
    asm volatile("cp.async.cg.shared.global [%0], [%1], 16;" :: "r"(d), "l"(src));
}
#define CPA_COMMIT() asm volatile("cp.async.commit_group;" ::: "memory")
#define CPA_WAIT1()  asm volatile("cp.async.wait_group 1;" ::: "memory")
#define CPA_WAIT0()  asm volatile("cp.async.wait_group 0;" ::: "memory")

// Issue one tile into this warp's ring slot (3 x 16B per lane). ALWAYS commits
// (empty groups keep the per-thread group count consistent past the end).
#define ISSUE(tile, slot)                                                    \
    do {                                                                     \
        if ((tile) < nTiles) {                                               \
            const float4* s_ = p4 + (size_t)(tile) * SLOT_F4 + lane;         \
            float4*       d_ = wst + (slot) * SLOT_F4 + lane;                \
            cpa16(d_,      s_);                                              \
            cpa16(d_ + 32, s_ + 32);                                         \
            cpa16(d_ + 64, s_ + 64);                                         \
        }                                                                    \
        CPA_COMMIT();                                                        \
    } while (0)

__global__ void __cluster_dims__(2, 1, 1) __launch_bounds__(THREADS, 1)
k_fused(const float* __restrict__ x, const float* __restrict__ W,
        const float* __restrict__ bias, float* __restrict__ out,
        int N, int nTiles, int tailStart, float invN)
{
    extern __shared__ float4 stg[];     // [NWARP][NSLOT][SLOT_F4]

    __shared__ float sWt[BINS * CLS];   // W transposed: sWt[k*CLS + c]
    __shared__ int   sh[NWARP * BINS];  // per-warp sub-histograms
    __shared__ float sred[NWARP][6];
    __shared__ float sblk[6];           // this CTA's mn0..2, mx0..2
    __shared__ float sfin[6];           // cluster-combined
    __shared__ int   hfin[BINS];
    __shared__ float sc[BINS];

    cg::cluster_group cluster = cg::this_cluster();
    const int rank = cluster.block_rank();   // 0 or 1
    const int bat  = blockIdx.y;
    const int tid  = threadIdx.x;
    const int lane = tid & 31, warp = tid >> 5;
    const int gwarp = rank * NWARP + warp;   // 0..63 across cluster
    const int ctid  = rank * THREADS + tid;  // 0..2047 across cluster

    const float*  xb = x + (size_t)bat * 3u * (size_t)N;
    const float4* p4 = (const float4*)xb;
    float4* wst = stg + warp * (NSLOT * SLOT_F4);   // this warp's ring

    if (rank == 0) {
        for (int i = tid; i < CLS * BINS; i += THREADS) {
            int c = i >> 6, k = i & 63;
            sWt[k * CLS + c] = W[i];
        }
    }
    for (int i = tid; i < NWARP * BINS; i += THREADS) sh[i] = 0;

    // ============== Pass 1: min/max via warp-private cp.async ring ========
    const float FMAX = 3.402823466e38f;
    float mn0 = FMAX, mn1 = FMAX, mn2 = FMAX;
    float mx0 = -FMAX, mx1 = -FMAX, mx2 = -FMAX;

    ISSUE(gwarp,           0);
    ISSUE(gwarp + GSTRIDE, 1);
    {
        int k = 0;
        for (int tc = gwarp; tc < nTiles; tc += GSTRIDE, k++) {
            CPA_WAIT1();                 // oldest group (tile k) complete
            __syncwarp();
            int slot = k % NSLOT;
            ISSUE(tc + 2 * GSTRIDE, (k + 2) % NSLOT);   // != consume slot

            const float* f = (const float*)(wst + slot * SLOT_F4) + lane * 12;
            float4 q0 = *(const float4*)(f + 0);
            float4 q1 = *(const float4*)(f + 4);
            float4 q2 = *(const float4*)(f + 8);
            // points: (q0.x,q0.y,q0.z)(q0.w,q1.x,q1.y)(q1.z,q1.w,q2.x)(q2.y,q2.z,q2.w)
            mn0 = fminf(mn0, fminf(fminf(q0.x, q0.w), fminf(q1.z, q2.y)));
            mx0 = fmaxf(mx0, fmaxf(fmaxf(q0.x, q0.w), fmaxf(q1.z, q2.y)));
            mn1 = fminf(mn1, fminf(fminf(q0.y, q1.x), fminf(q1.w, q2.z)));
            mx1 = fmaxf(mx1, fmaxf(fmaxf(q0.y, q1.x), fmaxf(q1.w, q2.z)));
            mn2 = fminf(mn2, fminf(fminf(q0.z, q1.y), fminf(q2.x, q2.w)));
            mx2 = fmaxf(mx2, fmaxf(fmaxf(q0.z, q1.y), fmaxf(q2.x, q2.w)));
        }
        CPA_WAIT0();
        __syncwarp();
    }

    // Tail points
    for (int j = tailStart + ctid; j < N; j += 2 * THREADS) {
        float vx = xb[3 * j + 0], vy = xb[3 * j + 1], vz = xb[3 * j + 2];
        mn0 = fminf(mn0, vx); mx0 = fmaxf(mx0, vx);
        mn1 = fminf(mn1, vy); mx1 = fmaxf(mx1, vy);
        mn2 = fminf(mn2, vz); mx2 = fmaxf(mx2, vz);
    }

    #pragma unroll
    for (int off = 16; off > 0; off >>= 1) {
        mn0 = fminf(mn0, __shfl_xor_sync(0xffffffffu, mn0, off));
        mn1 = fminf(mn1, __shfl_xor_sync(0xffffffffu, mn1, off));
        mn2 = fminf(mn2, __shfl_xor_sync(0xffffffffu, mn2, off));
        mx0 = fmaxf(mx0, __shfl_xor_sync(0xffffffffu, mx0, off));
        mx1 = fmaxf(mx1, __shfl_xor_sync(0xffffffffu, mx1, off));
        mx2 = fmaxf(mx2, __shfl_xor_sync(0xffffffffu, mx2, off));
    }
    if (lane == 0) {
        sred[warp][0] = mn0; sred[warp][1] = mn1; sred[warp][2] = mn2;
        sred[warp][3] = mx0; sred[warp][4] = mx1; sred[warp][5] = mx2;
    }
    __syncthreads();
    if (warp == 0) {   // NWARP == 32
        float v0 = sred[lane][0], v1 = sred[lane][1], v2 = sred[lane][2];
        float v3 = sred[lane][3], v4 = sred[lane][4], v5 = sred[lane][5];
        #pragma unroll
        for (int off = 16; off > 0; off >>= 1) {
            v0 = fminf(v0, __shfl_xor_sync(0xffffffffu, v0, off));
            v1 = fminf(v1, __shfl_xor_sync(0xffffffffu, v1, off));
            v2 = fminf(v2, __shfl_xor_sync(0xffffffffu, v2, off));
            v3 = fmaxf(v3, __shfl_xor_sync(0xffffffffu, v3, off));
            v4 = fmaxf(v4, __shfl_xor_sync(0xffffffffu, v4, off));
            v5 = fmaxf(v5, __shfl_xor_sync(0xffffffffu, v5, off));
        }
        if (lane == 0) {
            sblk[0] = v0; sblk[1] = v1; sblk[2] = v2;
            sblk[3] = v3; sblk[4] = v4; sblk[5] = v5;
        }
    }

    // ---- Cluster exchange of min/max ----
    cluster.sync();
    if (tid < 3) {
        const float* peer = cluster.map_shared_rank(sblk, rank ^ 1);
        sfin[tid]     = fminf(sblk[tid],     peer[tid]);
        sfin[tid + 3] = fmaxf(sblk[tid + 3], peer[tid + 3]);
    }
    __syncthreads();
    const float fm0 = sfin[0], fm1 = sfin[1], fm2 = sfin[2];
    // Shrunken scale + interior bias (no clamps) + magic-number floor
    // (FADD instead of F2I): z = fmaf(v,s,t) + 2^23, bin bits in mantissa.
    const float MAGIC = 8388608.0f;  // 2^23
    const float s0 = 3.99999f / (sfin[3] - fm0);
    const float s1 = 3.99999f / (sfin[4] - fm1);
    const float s2 = 3.99999f / (sfin[5] - fm2);
    const float t0 = (1e-6f - 0.5f) - fm0 * s0;
    const float t1 = (1e-6f - 0.5f) - fm1 * s1;
    const float t2 = (1e-6f - 0.5f) - fm2 * s2;

    // ============== Pass 2: histogram via warp-private cp.async ring ======
    int* myh = &sh[warp << 6];

    #define BIN3(px, py, pz)                                                 \
        do {                                                                 \
            float z0_ = fmaf((px), s0, t0) + MAGIC;                          \
            float z1_ = fmaf((py), s1, t1) + MAGIC;                          \
            float z2_ = fmaf((pz), s2, t2) + MAGIC;                          \
            unsigned u0_ = __float_as_uint(z0_) & 3u;                        \
            unsigned u1_ = __float_as_uint(z1_) & 3u;                        \
            unsigned u2_ = __float_as_uint(z2_) & 3u;                        \
            atomicAdd(&myh[(u0_ << 4) | (u1_ << 2) | u2_], 1);               \
        } while (0)

    ISSUE(gwarp,           0);
    ISSUE(gwarp + GSTRIDE, 1);
    {
        int k = 0;
        for (int tc = gwarp; tc < nTiles; tc += GSTRIDE, k++) {
            CPA_WAIT1();
            __syncwarp();
            int slot = k % NSLOT;
            ISSUE(tc + 2 * GSTRIDE, (k + 2) % NSLOT);

            const float* f = (const float*)(wst + slot * SLOT_F4) + lane * 12;
            float4 q0 = *(const float4*)(f + 0);
            float4 q1 = *(const float4*)(f + 4);
            float4 q2 = *(const float4*)(f + 8);
            BIN3(q0.x, q0.y, q0.z);
            BIN3(q0.w, q1.x, q1.y);
            BIN3(q1.z, q1.w, q2.x);
            BIN3(q2.y, q2.z, q2.w);
        }
        CPA_WAIT0();
        __syncwarp();
    }
    // Tail points
    for (int j = tailStart + ctid; j < N; j += 2 * THREADS) {
        BIN3(xb[3 * j + 0], xb[3 * j + 1], xb[3 * j + 2]);
    }
    __syncthreads();

    if (tid < BINS) {
        int s = 0;
        #pragma unroll
        for (int w = 0; w < NWARP; w++) s += sh[(w << 6) + tid];
        hfin[tid] = s;
    }

    // ---- Cluster hist merge + epilogue (rank 0) ----
    cluster.sync();
    if (rank == 0 && tid < BINS) {
        const int* peer = cluster.map_shared_rank(hfin, 1);
        sc[tid] = (float)(hfin[tid] + peer[tid]) * invN;
    }
    cluster.sync();   // rank 1 must not exit before rank 0 read its smem

    if (rank == 0) {
        __syncthreads();
        if (tid < CLS) {
            float acc = bias[tid];
            #pragma unroll
            for (int k = 0; k < BINS; k++)
                acc = fmaf(sc[k], sWt[k * CLS + tid], acc);
            out[bat * CLS + tid] = acc;
        }
    }
}

extern "C" void kernel_launch(void* const* d_in, const int* in_sizes, int n_in,
                              void* d_out, int out_size) {
    const float* x = (const float*)d_in[0];
    const float* W = (const float*)d_in[1];
    const float* b = (const float*)d_in[2];
    float* out = (float*)d_out;

    int N = in_sizes[0] / (BATCH * 3);   // 100000
    int nf4    = ((3 * N) % 4 == 0) ? (3 * N) / 4 : 0;
    int nTiles = nf4 / 96;               // tiles of 128 points
    int tailStart = nTiles * 128;

    cudaFuncSetAttribute(k_fused, cudaFuncAttributeMaxDynamicSharedMemorySize,
                         DYN_BYTES);

    dim3 grid(2, BATCH);
    k_fused<<<grid, THREADS, DYN_BYTES>>>(x, W, b, out, N, nTiles, tailStart,
                                          1.0f / (float)N);
}